// round 11
// baseline (speedup 1.0000x reference)
#include <cuda_runtime.h>
#include <math.h>
#include <stdint.h>

#define N_TOK 2048
#define D_DIM 1024
#define F_DIM 2048
#define N_EXP 8
#define N_HEAD 16
#define S_LEN 1024

// ---------------- fp32 scratch ----------------------------------------------
__device__ float g_q[N_TOK * D_DIM];
__device__ float g_k[N_TOK * D_DIM];
__device__ float g_v[N_TOK * D_DIM];
__device__ float g_attno[N_TOK * D_DIM];
__device__ float g_gated[N_TOK * D_DIM];
__device__ float g_attnp[N_TOK * D_DIM];
__device__ float g_x[N_TOK * D_DIM];
__device__ float g_hh[N_TOK * F_DIM];
__device__ float g_moe[N_TOK * D_DIM];
__device__ int   g_chosen[N_TOK];
__device__ int   g_counts[N_EXP];
__device__ int   g_offsets[N_EXP];
__device__ int   g_cursor[N_EXP];
__device__ int   g_p2t[N_TOK];
__device__ int   g_p2e[N_TOK];

// ================= helpers ====================================================
__device__ __forceinline__ uint32_t smem_u32(const void* p) {
    uint32_t a;
    asm("{ .reg .u64 t; cvta.to.shared.u64 t, %1; cvt.u32.u64 %0, t; }" : "=r"(a) : "l"(p));
    return a;
}
#define CP_ASYNC16(dst, src) \
    asm volatile("cp.async.cg.shared.global [%0], [%1], 16;" :: "r"(dst), "l"(src))
#define CP_COMMIT() asm volatile("cp.async.commit_group;" ::: "memory")
#define CP_WAIT0()  asm volatile("cp.async.wait_group 0;" ::: "memory")
#define CP_WAIT1()  asm volatile("cp.async.wait_group 1;" ::: "memory")

__device__ __forceinline__ void ldsm4(uint32_t* r, uint32_t addr) {
    asm volatile("ldmatrix.sync.aligned.m8n8.x4.shared.b16 {%0,%1,%2,%3}, [%4];"
        : "=r"(r[0]), "=r"(r[1]), "=r"(r[2]), "=r"(r[3]) : "r"(addr));
}
__device__ __forceinline__ uint32_t to_tf32(float f) {
    uint32_t r;
    asm("cvt.rna.tf32.f32 %0, %1;" : "=r"(r) : "f"(f));
    return r;
}
__device__ __forceinline__ float lds32(uint32_t a) {
    float v;
    asm("ld.shared.f32 %0, [%1];" : "=f"(v) : "r"(a));
    return v;
}
__device__ __forceinline__ void mma_tf32(float* c, const uint32_t* a, uint32_t b0, uint32_t b1) {
    asm volatile("mma.sync.aligned.m16n8k8.row.col.f32.tf32.tf32.f32 "
        "{%0,%1,%2,%3}, {%4,%5,%6,%7}, {%8,%9}, {%0,%1,%2,%3};"
        : "+f"(c[0]), "+f"(c[1]), "+f"(c[2]), "+f"(c[3])
        : "r"(a[0]), "r"(a[1]), "r"(a[2]), "r"(a[3]), "r"(b0), "r"(b1));
}

// ================= TF32 GEMM: 128x128 tile, A[*,K] fp32, B[K,N] fp32 =========
// smem: A [128][36] fp32 (pitch 144B), B [32][136] fp32 (pitch 544B)
#define TF_A_OFF 0
#define TF_B_OFF 18432
#define TF_STAGE 35840
#define TF_SMEM (2 * TF_STAGE)

template <class AROW, class EPI>
__device__ __forceinline__ void mma_body(const float* __restrict__ A,
                                         const float* __restrict__ B,
                                         int K, int N, int col0, AROW arow, EPI epi)
{
    extern __shared__ char smem[];
    const uint32_t sb = smem_u32(smem);
    const int t = threadIdx.x;
    const int lane = t & 31, warp = t >> 5;
    const int warpM = warp >> 2, warpN = warp & 3;

    // loaders: A 128 rows x 32 floats (2 thr/row), B 32 rows x 128 floats (8 thr/row)
    const int arow_i = t >> 1, ahalf = t & 1;
    const int aR = arow(arow_i);
    const float* srcA = A + (size_t)aR * K + ahalf * 16;
    const uint32_t adst = TF_A_OFF + arow_i * 144 + ahalf * 64;
    const int brow = t >> 3, bseg = t & 7;
    const float* srcB = B + (size_t)brow * N + col0 + bseg * 16;
    const uint32_t bdst = TF_B_OFF + brow * 544 + bseg * 64;

    auto issue_stage = [&](int k0, int buf) {
        const uint32_t s = sb + buf * TF_STAGE;
#pragma unroll
        for (int i = 0; i < 4; ++i)
            CP_ASYNC16(s + adst + i * 16, srcA + k0 + i * 4);
        const size_t bko = (size_t)k0 * N;
#pragma unroll
        for (int i = 0; i < 4; ++i)
            CP_ASYNC16(s + bdst + i * 16, srcB + bko + i * 4);
        CP_COMMIT();
    };

    const int a_row_l = (lane & 7) + ((lane >> 3) & 1) * 8;
    const int a_k_l   = ((lane >> 4) & 1) * 4;

    float acc[4][4][4] = {};

    issue_stage(0, 0);
    const int NS = K >> 5;
    int buf = 0;
    for (int s = 0; s < NS; ++s) {
        CP_WAIT0();
        __syncthreads();
        if (s + 1 < NS) issue_stage((s + 1) * 32, buf ^ 1);

        const uint32_t sbase = sb + buf * TF_STAGE;
#pragma unroll
        for (int kk = 0; kk < 4; ++kk) {
            uint32_t a[4][4];
#pragma unroll
            for (int mi = 0; mi < 4; ++mi) {
                const uint32_t ro = TF_A_OFF + (uint32_t)(warpM * 64 + mi * 16 + a_row_l) * 144
                                  + (kk * 8 + a_k_l) * 4;
                uint32_t r[4];
                ldsm4(r, sbase + ro);
#pragma unroll
                for (int q = 0; q < 4; ++q) a[mi][q] = to_tf32(__uint_as_float(r[q]));
            }
#pragma unroll
            for (int nj = 0; nj < 4; ++nj) {
                const uint32_t b0a = sbase + TF_B_OFF + (uint32_t)(kk * 8 + (lane & 3)) * 544
                                   + (uint32_t)(warpN * 32 + nj * 8 + (lane >> 2)) * 4;
                const uint32_t b0 = to_tf32(lds32(b0a));
                const uint32_t b1 = to_tf32(lds32(b0a + 4 * 544));
#pragma unroll
                for (int mi = 0; mi < 4; ++mi)
                    mma_tf32(acc[mi][nj], a[mi], b0, b1);
            }
        }
        __syncthreads();
        buf ^= 1;
    }

#pragma unroll
    for (int mi = 0; mi < 4; ++mi)
#pragma unroll
        for (int nj = 0; nj < 4; ++nj) {
            const int r0 = warpM * 64 + mi * 16 + (lane >> 2);
            const int c  = warpN * 32 + nj * 8 + (lane & 3) * 2;
            epi(r0,     c, acc[mi][nj][0], acc[mi][nj][1]);
            epi(r0 + 8, c, acc[mi][nj][2], acc[mi][nj][3]);
        }
}

// ---------------- dense GEMM (batched up to 3 via z) -------------------------
// mode 0: C = acc (+bias); mode 1: C = sigmoid(acc+bias) * aux
struct DenseArgs {
    const float* B[3];
    const float* bias[3];
    const float* aux[3];
    float* C[3];
    int mode[3];
};
__global__ __launch_bounds__(256)
void gemm_tf_dense(const float* __restrict__ A, DenseArgs da, int N, int K)
{
    const int z = blockIdx.z;
    const int row0 = blockIdx.y * 128, col0 = blockIdx.x * 128;
    const float* B = da.B[z];
    const float* bias = da.bias[z];
    const float* aux = da.aux[z];
    float* C = da.C[z];
    const int mode = da.mode[z];
    auto arow = [&](int r) { return row0 + r; };
    auto epi = [&](int m, int c, float v0, float v1) {
        const int gc = col0 + c;
        const size_t base = (size_t)(row0 + m) * N + gc;
        if (bias) { v0 += bias[gc]; v1 += bias[gc + 1]; }
        if (mode == 1) {
            float2 a = *(const float2*)&aux[base];
            v0 = a.x / (1.f + __expf(-v0));
            v1 = a.y / (1.f + __expf(-v1));
        }
        *(float2*)&C[base] = make_float2(v0, v1);
    };
    mma_body(A, B, K, N, col0, arow, epi);
}

// ---------------- expert GEMM 1: hh = x @ w1[e] + b1 -------------------------
__global__ __launch_bounds__(256)
void gemm_tf_e1(const float* __restrict__ x, const float* __restrict__ w1,
                const float* __restrict__ b1, float* __restrict__ hh)
{
    const int e = blockIdx.z;
    const int cnt = g_counts[e];
    const int rt = blockIdx.y * 128;
    if (rt >= cnt) return;
    const int off = g_offsets[e];
    const int col0 = blockIdx.x * 128;
    const float* B = w1 + (size_t)e * D_DIM * F_DIM;
    const float* b1e = b1 + (size_t)e * F_DIM;
    auto arow = [&](int r) {
        int rr = rt + r; if (rr >= cnt) rr = cnt - 1;
        return g_p2t[off + rr];
    };
    auto epi = [&](int m, int c, float v0, float v1) {
        if (rt + m >= cnt) return;
        const int gc = col0 + c;
        const size_t base = (size_t)(off + rt + m) * F_DIM + gc;
        *(float2*)&hh[base] = make_float2(v0 + b1e[gc], v1 + b1e[gc + 1]);
    };
    mma_body(x, B, D_DIM, F_DIM, col0, arow, epi);
}

// ---------------- expert GEMM 2 + residual scatter ---------------------------
__global__ __launch_bounds__(256)
void gemm_tf_e2(const float* __restrict__ hh, const float* __restrict__ w2,
                const float* __restrict__ b2, const float* __restrict__ res_scale,
                const float* __restrict__ x, float* __restrict__ moe)
{
    const int e = blockIdx.z;
    const int cnt = g_counts[e];
    const int rt = blockIdx.y * 128;
    if (rt >= cnt) return;
    const int off = g_offsets[e];
    const int col0 = blockIdx.x * 128;
    const float* B = w2 + (size_t)e * F_DIM * D_DIM;
    const float* b2e = b2 + (size_t)e * D_DIM;
    const float rsc = res_scale[e];
    auto arow = [&](int r) {
        int rr = rt + r; if (rr >= cnt) rr = cnt - 1;
        return off + rr;
    };
    auto epi = [&](int m, int c, float v0, float v1) {
        if (rt + m >= cnt) return;
        const int tok = g_p2t[off + rt + m];
        const int gc = col0 + c;
        const size_t base = (size_t)tok * D_DIM + gc;
        float2 xr = *(const float2*)&x[base];
        *(float2*)&moe[base] = make_float2((v0 + b2e[gc]) * rsc + xr.x,
                                           (v1 + b2e[gc + 1]) * rsc + xr.y);
    };
    mma_body(hh, B, F_DIM, D_DIM, col0, arow, epi);
}

// ================= TF32 MMA flash attention ==================================
// smem: Q [128][68] fp32, K chunks [64][68] x2, V chunks [64][72] x2
#define AQ_OFF 0
#define AK_OFF(b) (34816 + (b) * 17408)
#define AV_OFF(b) (69632 + (b) * 18432)
#define AQSC 106496
#define ATTN_SMEM (106496 + 512)

__global__ __launch_bounds__(256, 1)
void attn_tf(const float* __restrict__ q, const float* __restrict__ k,
             const float* __restrict__ v, const float* __restrict__ scale_w,
             float* __restrict__ out)
{
    extern __shared__ char smem[];
    const uint32_t sb = smem_u32(smem);
    float* qsc = (float*)(smem + AQSC);
    const int t = threadIdx.x, lane = t & 31, warp = t >> 5;
    const int h = blockIdx.y & 15, b = blockIdx.y >> 4;
    const int qtok0 = b * S_LEN + blockIdx.x * 128;
    const size_t headoff = (size_t)h * 64;

    // Q load (own cp.async group)
    {
        const int row = t >> 1, half = t & 1;
        const float* src = q + (size_t)(qtok0 + row) * D_DIM + headoff + half * 32;
        const uint32_t dq = AQ_OFF + (uint32_t)row * 272 + half * 128;
#pragma unroll
        for (int i = 0; i < 8; ++i)
            CP_ASYNC16(sb + dq + i * 16, src + i * 4);
        CP_COMMIT();
    }
    auto issueKV = [&](int c, int buf) {
        const int row = t >> 2, seg = t & 3;
        const size_t so = (size_t)(b * S_LEN + c * 64 + row) * D_DIM + headoff + seg * 16;
        const uint32_t dk = AK_OFF(buf) + (uint32_t)row * 272 + seg * 64;
        const uint32_t dv = AV_OFF(buf) + (uint32_t)row * 288 + seg * 64;
#pragma unroll
        for (int i = 0; i < 4; ++i) {
            CP_ASYNC16(sb + dk + i * 16, k + so + i * 4);
            CP_ASYNC16(sb + dv + i * 16, v + so + i * 4);
        }
        CP_COMMIT();
    };
    issueKV(0, 0);
    CP_WAIT1();      // Q ready
    __syncthreads();

    if (t < 128) {
        float s = 0.f;
        const float* qrow = (const float*)(smem + AQ_OFF) + t * 68;
        for (int d = 0; d < 64; ++d) s += qrow[d] * __ldg(&scale_w[h * 64 + d]);
        qsc[t] = 0.25f / (1.f + __expf(-s));
    }

    const int a_row_l = (lane & 7) + ((lane >> 3) & 1) * 8;
    const int a_k_l   = ((lane >> 4) & 1) * 4;
    const int r0loc = warp * 16 + (lane >> 2);

    float s[8][4];
    float o[8][4] = {};
    float m0 = -1e30f, m1 = -1e30f, l0 = 0.f, l1 = 0.f;

    for (int c = 0; c < 16; ++c) {
        CP_WAIT0();
        __syncthreads();
        if (c < 15) issueKV(c + 1, (c + 1) & 1);
        const uint32_t kb = sb + AK_OFF(c & 1);
        const uint32_t vb = sb + AV_OFF(c & 1);

        // ---- S = Q K^T ----
#pragma unroll
        for (int j = 0; j < 8; ++j) { s[j][0] = s[j][1] = s[j][2] = s[j][3] = 0.f; }
#pragma unroll
        for (int kk = 0; kk < 8; ++kk) {
            uint32_t a[4], r[4];
            const uint32_t ao = (uint32_t)(warp * 16 + a_row_l) * 272 + (kk * 8 + a_k_l) * 4;
            ldsm4(r, sb + AQ_OFF + ao);
#pragma unroll
            for (int qd = 0; qd < 4; ++qd) a[qd] = to_tf32(__uint_as_float(r[qd]));
#pragma unroll
            for (int p = 0; p < 4; ++p) {
                // ldmatrix.x4 on K gives b-frags for n-blocks 2p and 2p+1
                const uint32_t ro = (uint32_t)(p * 16 + a_row_l) * 272 + (kk * 8 + a_k_l) * 4;
                uint32_t br[4];
                ldsm4(br, kb + ro);
                uint32_t b00 = to_tf32(__uint_as_float(br[0]));
                uint32_t b01 = to_tf32(__uint_as_float(br[1]));
                uint32_t b10 = to_tf32(__uint_as_float(br[2]));
                uint32_t b11 = to_tf32(__uint_as_float(br[3]));
                mma_tf32(s[2 * p],     a, b00, b10);
                mma_tf32(s[2 * p + 1], a, b01, b11);
            }
        }
        // row scale
        const float f0 = qsc[r0loc], f1 = qsc[r0loc + 8];
#pragma unroll
        for (int j = 0; j < 8; ++j) { s[j][0] *= f0; s[j][1] *= f0; s[j][2] *= f1; s[j][3] *= f1; }
        // online softmax
        float rm0 = -1e30f, rm1 = -1e30f;
#pragma unroll
        for (int j = 0; j < 8; ++j) {
            rm0 = fmaxf(rm0, fmaxf(s[j][0], s[j][1]));
            rm1 = fmaxf(rm1, fmaxf(s[j][2], s[j][3]));
        }
        rm0 = fmaxf(rm0, __shfl_xor_sync(0xffffffffu, rm0, 1));
        rm0 = fmaxf(rm0, __shfl_xor_sync(0xffffffffu, rm0, 2));
        rm1 = fmaxf(rm1, __shfl_xor_sync(0xffffffffu, rm1, 1));
        rm1 = fmaxf(rm1, __shfl_xor_sync(0xffffffffu, rm1, 2));
        const float nm0 = fmaxf(m0, rm0), nm1 = fmaxf(m1, rm1);
        const float e0 = __expf(m0 - nm0), e1v = __expf(m1 - nm1);
        float sum0 = 0.f, sum1 = 0.f;
#pragma unroll
        for (int j = 0; j < 8; ++j) {
            s[j][0] = __expf(s[j][0] - nm0); sum0 += s[j][0];
            s[j][1] = __expf(s[j][1] - nm0); sum0 += s[j][1];
            s[j][2] = __expf(s[j][2] - nm1); sum1 += s[j][2];
            s[j][3] = __expf(s[j][3] - nm1); sum1 += s[j][3];
        }
        sum0 += __shfl_xor_sync(0xffffffffu, sum0, 1);
        sum0 += __shfl_xor_sync(0xffffffffu, sum0, 2);
        sum1 += __shfl_xor_sync(0xffffffffu, sum1, 1);
        sum1 += __shfl_xor_sync(0xffffffffu, sum1, 2);
        l0 = l0 * e0 + sum0;
        l1 = l1 * e1v + sum1;
        m0 = nm0; m1 = nm1;
#pragma unroll
        for (int j = 0; j < 8; ++j) { o[j][0] *= e0; o[j][1] *= e0; o[j][2] *= e1v; o[j][3] *= e1v; }

        // ---- O += P V ----
#pragma unroll
        for (int kk = 0; kk < 8; ++kk) {
            // A-frag from S registers via intra-warp shuffles
            const int jpar = lane & 1;
            const int srcl  = (lane & 28) | ((lane & 3) >> 1);
            const int srcl2 = srcl + 2;
            float f0a = __shfl_sync(0xffffffffu, s[kk][0], srcl);
            float f1a = __shfl_sync(0xffffffffu, s[kk][1], srcl);
            float f2a = __shfl_sync(0xffffffffu, s[kk][2], srcl);
            float f3a = __shfl_sync(0xffffffffu, s[kk][3], srcl);
            float g0a = __shfl_sync(0xffffffffu, s[kk][0], srcl2);
            float g1a = __shfl_sync(0xffffffffu, s[kk][1], srcl2);
            float g2a = __shfl_sync(0xffffffffu, s[kk][2], srcl2);
            float g3a = __shfl_sync(0xffffffffu, s[kk][3], srcl2);
            uint32_t a[4];
            a[0] = to_tf32(jpar ? f1a : f0a);
            a[1] = to_tf32(jpar ? f3a : f2a);
            a[2] = to_tf32(jpar ? g1a : g0a);
            a[3] = to_tf32(jpar ? g3a : g2a);
#pragma unroll
            for (int nj = 0; nj < 8; ++nj) {
                const uint32_t b0a = vb + (uint32_t)(kk * 8 + (lane & 3)) * 288
                                   + (uint32_t)(nj * 8 + (lane >> 2)) * 4;
                const uint32_t b0 = to_tf32(lds32(b0a));
                const uint32_t b1 = to_tf32(lds32(b0a + 4 * 288));
                mma_tf32(o[nj], a, b0, b1);
            }
        }
    }

    const float inv0 = 1.f / l0, inv1 = 1.f / l1;
    const int tok0 = qtok0 + r0loc, tok1 = tok0 + 8;
#pragma unroll
    for (int j = 0; j < 8; ++j) {
        const size_t col = headoff + j * 8 + (lane & 3) * 2;
        *(float2*)&out[(size_t)tok0 * D_DIM + col] = make_float2(o[j][0] * inv0, o[j][1] * inv0);
        *(float2*)&out[(size_t)tok1 * D_DIM + col] = make_float2(o[j][2] * inv1, o[j][3] * inv1);
    }
}

// ---------------- layernorm over residual sum -------------------------------
__global__ void ln2_kernel(const float* __restrict__ a, const float* __restrict__ b,
                           const float* __restrict__ g, const float* __restrict__ be,
                           float* __restrict__ out, int D)
{
    const int row = blockIdx.x, t = threadIdx.x;
    __shared__ float red[256];
    __shared__ float s_mean, s_rstd;
    float s1 = 0.f, s2 = 0.f;
    for (int i = t; i < D; i += 256) {
        float v = a[(size_t)row * D + i] + b[(size_t)row * D + i];
        s1 += v; s2 += v * v;
    }
    red[t] = s1; __syncthreads();
    for (int o = 128; o; o >>= 1) { if (t < o) red[t] += red[t + o]; __syncthreads(); }
    if (t == 0) s_mean = red[0] / D;
    __syncthreads();
    red[t] = s2; __syncthreads();
    for (int o = 128; o; o >>= 1) { if (t < o) red[t] += red[t + o]; __syncthreads(); }
    if (t == 0) {
        float var = red[0] / D - s_mean * s_mean;
        s_rstd = rsqrtf(var + 1e-5f);
    }
    __syncthreads();
    for (int i = t; i < D; i += 256) {
        float v = a[(size_t)row * D + i] + b[(size_t)row * D + i];
        out[(size_t)row * D + i] = (v - s_mean) * s_rstd * g[i] + be[i];
    }
}

// ---------------- MoE routing ------------------------------------------------
__global__ void reset_kernel() { if (threadIdx.x < N_EXP) g_counts[threadIdx.x] = 0; }

__global__ void moe_gate_kernel(const float* __restrict__ x, const float* __restrict__ W,
                                const float* __restrict__ bias)
{
    const int n = blockIdx.x, t = threadIdx.x;
    const int e = t >> 5, lane = t & 31;
    float acc = 0.f;
    for (int d = lane; d < D_DIM; d += 32) acc += x[(size_t)n * D_DIM + d] * W[d * N_EXP + e];
    for (int o = 16; o; o >>= 1) acc += __shfl_down_sync(0xffffffffu, acc, o);
    __shared__ float lg[N_EXP];
    if (lane == 0) lg[e] = acc + bias[e];
    __syncthreads();
    if (t == 0) {
        int i1 = 0; float v1 = lg[0];
        for (int i = 1; i < N_EXP; ++i) if (lg[i] > v1) { v1 = lg[i]; i1 = i; }
        int i2 = -1; float v2 = -1e30f;
        for (int i = 0; i < N_EXP; ++i) {
            if (i == i1) continue;
            if (lg[i] > v2) { v2 = lg[i]; i2 = i; }
        }
        int c = (i1 > i2) ? i1 : i2;
        g_chosen[n] = c;
        atomicAdd(&g_counts[c], 1);
    }
}

__global__ void scan_kernel()
{
    if (threadIdx.x == 0) {
        int s = 0;
        for (int e = 0; e < N_EXP; ++e) { g_offsets[e] = s; g_cursor[e] = s; s += g_counts[e]; }
    }
}

__global__ void scatter_kernel()
{
    int n = blockIdx.x * 256 + threadIdx.x;
    if (n < N_TOK) {
        int c = g_chosen[n];
        int p = atomicAdd(&g_cursor[c], 1);
        g_p2t[p] = n;
        g_p2e[p] = c;
    }
}

// ---------------- per-expert LN + exact GELU (in-place) ----------------------
__global__ void ln_gelu_kernel(float* __restrict__ hh, const float* __restrict__ ln_g,
                               const float* __restrict__ ln_b)
{
    const int p = blockIdx.x, t = threadIdx.x;
    const int e = g_p2e[p];
    float* row = hh + (size_t)p * F_DIM;
    const float* gg = ln_g + (size_t)e * F_DIM;
    const float* bb = ln_b + (size_t)e * F_DIM;
    __shared__ float red[256];
    __shared__ float s_mean, s_rstd;
    float s1 = 0.f, s2 = 0.f;
    for (int i = t; i < F_DIM; i += 256) { float v = row[i]; s1 += v; s2 += v * v; }
    red[t] = s1; __syncthreads();
    for (int o = 128; o; o >>= 1) { if (t < o) red[t] += red[t + o]; __syncthreads(); }
    if (t == 0) s_mean = red[0] / F_DIM;
    __syncthreads();
    red[t] = s2; __syncthreads();
    for (int o = 128; o; o >>= 1) { if (t < o) red[t] += red[t + o]; __syncthreads(); }
    if (t == 0) {
        float var = red[0] / F_DIM - s_mean * s_mean;
        s_rstd = rsqrtf(var + 1e-5f);
    }
    __syncthreads();
    for (int i = t; i < F_DIM; i += 256) {
        float tv = (row[i] - s_mean) * s_rstd * gg[i] + bb[i];
        row[i] = 0.5f * tv * (1.f + erff(tv * 0.70710678118654752f));
    }
}

// ---------------- host launcher ---------------------------------------------
extern "C" void kernel_launch(void* const* d_in, const int* in_sizes, int n_in,
                              void* d_out, int out_size)
{
    (void)in_sizes; (void)n_in; (void)out_size;
    const float* src        = (const float*)d_in[0];
    const float* q_w        = (const float*)d_in[1];
    const float* k_w        = (const float*)d_in[2];
    const float* v_w        = (const float*)d_in[3];
    const float* out_w      = (const float*)d_in[4];
    const float* gate_w     = (const float*)d_in[5];
    const float* gate_b     = (const float*)d_in[6];
    const float* scale_w    = (const float*)d_in[7];
    const float* n1_g       = (const float*)d_in[8];
    const float* n1_b       = (const float*)d_in[9];
    const float* n2_g       = (const float*)d_in[10];
    const float* n2_b       = (const float*)d_in[11];
    const float* moe_gate_w = (const float*)d_in[12];
    const float* moe_gate_b = (const float*)d_in[13];
    const float* w1         = (const float*)d_in[14];
    const float* b1         = (const float*)d_in[15];
    const float* ln_g       = (const float*)d_in[16];
    const float* ln_b       = (const float*)d_in[17];
    const float* w2         = (const float*)d_in[18];
    const float* b2         = (const float*)d_in[19];
    const float* res_scale  = (const float*)d_in[20];

    float *qb, *kb, *vb, *attno, *gated, *attnp, *xb, *hhb, *moeb;
    cudaGetSymbolAddress((void**)&qb, g_q);
    cudaGetSymbolAddress((void**)&kb, g_k);
    cudaGetSymbolAddress((void**)&vb, g_v);
    cudaGetSymbolAddress((void**)&attno, g_attno);
    cudaGetSymbolAddress((void**)&gated, g_gated);
    cudaGetSymbolAddress((void**)&attnp, g_attnp);
    cudaGetSymbolAddress((void**)&xb, g_x);
    cudaGetSymbolAddress((void**)&hhb, g_hh);
    cudaGetSymbolAddress((void**)&moeb, g_moe);

    cudaFuncSetAttribute(attn_tf, cudaFuncAttributeMaxDynamicSharedMemorySize, ATTN_SMEM);
    cudaFuncSetAttribute(gemm_tf_dense, cudaFuncAttributeMaxDynamicSharedMemorySize, TF_SMEM);
    cudaFuncSetAttribute(gemm_tf_e1, cudaFuncAttributeMaxDynamicSharedMemorySize, TF_SMEM);
    cudaFuncSetAttribute(gemm_tf_e2, cudaFuncAttributeMaxDynamicSharedMemorySize, TF_SMEM);

    reset_kernel<<<1, 32>>>();

    // QKV (batched z=3) — weights consumed directly in natural [K,N] layout
    {
        DenseArgs da = {};
        da.B[0] = q_w; da.B[1] = k_w; da.B[2] = v_w;
        da.C[0] = qb; da.C[1] = kb; da.C[2] = vb;
        gemm_tf_dense<<<dim3(8, 16, 3), 256, TF_SMEM>>>(src, da, D_DIM, D_DIM);
    }

    attn_tf<<<dim3(8, 32), 256, ATTN_SMEM>>>(qb, kb, vb, scale_w, attno);

    // gated = sigmoid(attno @ gate_w + gate_b) * attno
    {
        DenseArgs da = {};
        da.B[0] = gate_w; da.bias[0] = gate_b; da.aux[0] = attno;
        da.C[0] = gated; da.mode[0] = 1;
        gemm_tf_dense<<<dim3(8, 16, 1), 256, TF_SMEM>>>(attno, da, D_DIM, D_DIM);
    }

    // attnp = gated @ out_w
    {
        DenseArgs da = {};
        da.B[0] = out_w; da.C[0] = attnp; da.mode[0] = 0;
        gemm_tf_dense<<<dim3(8, 16, 1), 256, TF_SMEM>>>(gated, da, D_DIM, D_DIM);
    }

    ln2_kernel<<<N_TOK, 256>>>(src, attnp, n1_g, n1_b, xb, D_DIM);

    moe_gate_kernel<<<N_TOK, 256>>>(xb, moe_gate_w, moe_gate_b);
    scan_kernel<<<1, 32>>>();
    scatter_kernel<<<N_TOK / 256, 256>>>();

    gemm_tf_e1<<<dim3(F_DIM / 128, N_TOK / 128, N_EXP), 256, TF_SMEM>>>(xb, w1, b1, hhb);
    ln_gelu_kernel<<<N_TOK, 256>>>(hhb, ln_g, ln_b);
    gemm_tf_e2<<<dim3(D_DIM / 128, N_TOK / 128, N_EXP), 256, TF_SMEM>>>(
        hhb, w2, b2, res_scale, xb, moeb);

    ln2_kernel<<<N_TOK, 256>>>(xb, moeb, n2_g, n2_b, (float*)d_out, D_DIM);
}

// round 12
// speedup vs baseline: 1.4621x; 1.4621x over previous
#include <cuda_runtime.h>
#include <math.h>
#include <stdint.h>

#define N_TOK 2048
#define D_DIM 1024
#define F_DIM 2048
#define N_EXP 8
#define N_HEAD 16
#define S_LEN 1024

// ---------------- fp32 scratch ----------------------------------------------
__device__ float g_q[N_TOK * D_DIM];
__device__ float g_k[N_TOK * D_DIM];
__device__ float g_v[N_TOK * D_DIM];
__device__ float g_attno[N_TOK * D_DIM];
__device__ float g_gated[N_TOK * D_DIM];
__device__ float g_attnp[N_TOK * D_DIM];
__device__ float g_x[N_TOK * D_DIM];
__device__ float g_hh[N_TOK * F_DIM];
__device__ float g_moe[N_TOK * D_DIM];
__device__ int   g_chosen[N_TOK];
__device__ int   g_counts[N_EXP];
__device__ int   g_offsets[N_EXP];
__device__ int   g_cursor[N_EXP];
__device__ int   g_p2t[N_TOK];
__device__ int   g_p2e[N_TOK];

// ================= helpers ====================================================
__device__ __forceinline__ uint32_t smem_u32(const void* p) {
    uint32_t a;
    asm("{ .reg .u64 t; cvta.to.shared.u64 t, %1; cvt.u32.u64 %0, t; }" : "=r"(a) : "l"(p));
    return a;
}
#define CP_ASYNC16(dst, src) \
    asm volatile("cp.async.cg.shared.global [%0], [%1], 16;" :: "r"(dst), "l"(src))
#define CP_COMMIT() asm volatile("cp.async.commit_group;" ::: "memory")
#define CP_WAIT0()  asm volatile("cp.async.wait_group 0;" ::: "memory")
#define CP_WAIT1()  asm volatile("cp.async.wait_group 1;" ::: "memory")

__device__ __forceinline__ void ldsm4(uint32_t* r, uint32_t addr) {
    asm volatile("ldmatrix.sync.aligned.m8n8.x4.shared.b16 {%0,%1,%2,%3}, [%4];"
        : "=r"(r[0]), "=r"(r[1]), "=r"(r[2]), "=r"(r[3]) : "r"(addr));
}
__device__ __forceinline__ float lds32(uint32_t a) {
    float v;
    asm("ld.shared.f32 %0, [%1];" : "=f"(v) : "r"(a));
    return v;
}
// raw fp32 bits fed to tf32 MMA (HW truncates mantissa; no cvt instructions)
__device__ __forceinline__ void mma_tf32(float* c, const uint32_t* a, uint32_t b0, uint32_t b1) {
    asm volatile("mma.sync.aligned.m16n8k8.row.col.f32.tf32.tf32.f32 "
        "{%0,%1,%2,%3}, {%4,%5,%6,%7}, {%8,%9}, {%0,%1,%2,%3};"
        : "+f"(c[0]), "+f"(c[1]), "+f"(c[2]), "+f"(c[3])
        : "r"(a[0]), "r"(a[1]), "r"(a[2]), "r"(a[3]), "r"(b0), "r"(b1));
}

// ================= TF32 GEMM: 128x64 tile, A[*,K] fp32, B[K,N] fp32 ==========
// smem: A [128][36] fp32 (pitch 144B), B [32][72] fp32 (pitch 288B)
#define TF_A_OFF 0
#define TF_B_OFF 18432
#define TF_STAGE 27648
#define TF_SMEM (2 * TF_STAGE)

template <class AROW, class EPI>
__device__ __forceinline__ void mma_body(const float* __restrict__ A,
                                         const float* __restrict__ B,
                                         int K, int N, int col0, AROW arow, EPI epi)
{
    extern __shared__ char smem[];
    const uint32_t sb = smem_u32(smem);
    const int t = threadIdx.x;
    const int lane = t & 31, warp = t >> 5;
    const int warpM = warp >> 1, warpN = warp & 1;   // 4M x 2N, warp tile 32x32

    // loaders: A 128 rows x 32 floats (2 thr/row); B 32 rows x 64 floats (8 thr/row)
    const int arow_i = t >> 1, ahalf = t & 1;
    const int aR = arow(arow_i);
    const float* srcA = A + (size_t)aR * K + ahalf * 16;
    const uint32_t adst = TF_A_OFF + arow_i * 144 + ahalf * 64;
    const int brow = t >> 3, bseg = t & 7;
    const float* srcB = B + (size_t)brow * N + col0 + bseg * 8;
    const uint32_t bdst = TF_B_OFF + brow * 288 + bseg * 32;

    auto issue_stage = [&](int k0, int buf) {
        const uint32_t s = sb + buf * TF_STAGE;
#pragma unroll
        for (int i = 0; i < 4; ++i)
            CP_ASYNC16(s + adst + i * 16, srcA + k0 + i * 4);
        const size_t bko = (size_t)k0 * N;
        CP_ASYNC16(s + bdst,      srcB + bko);
        CP_ASYNC16(s + bdst + 16, srcB + bko + 4);
        CP_COMMIT();
    };

    const int a_row_l = (lane & 7) + ((lane >> 3) & 1) * 8;
    const int a_k_l   = ((lane >> 4) & 1) * 4;

    float acc[2][4][4] = {};

    issue_stage(0, 0);
    const int NS = K >> 5;
    int buf = 0;
    for (int s = 0; s < NS; ++s) {
        CP_WAIT0();
        __syncthreads();
        if (s + 1 < NS) issue_stage((s + 1) * 32, buf ^ 1);

        const uint32_t sbase = sb + buf * TF_STAGE;
#pragma unroll
        for (int kk = 0; kk < 4; ++kk) {
            uint32_t a[2][4];
#pragma unroll
            for (int mi = 0; mi < 2; ++mi) {
                const uint32_t ro = TF_A_OFF + (uint32_t)(warpM * 32 + mi * 16 + a_row_l) * 144
                                  + (kk * 8 + a_k_l) * 4;
                ldsm4(a[mi], sbase + ro);
            }
#pragma unroll
            for (int nj = 0; nj < 4; ++nj) {
                const uint32_t b0a = sbase + TF_B_OFF + (uint32_t)(kk * 8 + (lane & 3)) * 288
                                   + (uint32_t)(warpN * 32 + nj * 8 + (lane >> 2)) * 4;
                const uint32_t b0 = __float_as_uint(lds32(b0a));
                const uint32_t b1 = __float_as_uint(lds32(b0a + 4 * 288));
#pragma unroll
                for (int mi = 0; mi < 2; ++mi)
                    mma_tf32(acc[mi][nj], a[mi], b0, b1);
            }
        }
        __syncthreads();
        buf ^= 1;
    }

#pragma unroll
    for (int mi = 0; mi < 2; ++mi)
#pragma unroll
        for (int nj = 0; nj < 4; ++nj) {
            const int r0 = warpM * 32 + mi * 16 + (lane >> 2);
            const int c  = warpN * 32 + nj * 8 + (lane & 3) * 2;
            epi(r0,     c, acc[mi][nj][0], acc[mi][nj][1]);
            epi(r0 + 8, c, acc[mi][nj][2], acc[mi][nj][3]);
        }
}

// ---------------- dense GEMM (batched up to 3 via z) -------------------------
// mode 0: C = acc (+bias); mode 1: C = sigmoid(acc+bias) * aux
struct DenseArgs {
    const float* B[3];
    const float* bias[3];
    const float* aux[3];
    float* C[3];
    int mode[3];
};
__global__ __launch_bounds__(256)
void gemm_tf_dense(const float* __restrict__ A, DenseArgs da, int N, int K)
{
    const int z = blockIdx.z;
    const int row0 = blockIdx.y * 128, col0 = blockIdx.x * 64;
    const float* B = da.B[z];
    const float* bias = da.bias[z];
    const float* aux = da.aux[z];
    float* C = da.C[z];
    const int mode = da.mode[z];
    auto arow = [&](int r) { return row0 + r; };
    auto epi = [&](int m, int c, float v0, float v1) {
        const int gc = col0 + c;
        const size_t base = (size_t)(row0 + m) * N + gc;
        if (bias) { v0 += bias[gc]; v1 += bias[gc + 1]; }
        if (mode == 1) {
            float2 a = *(const float2*)&aux[base];
            v0 = a.x / (1.f + __expf(-v0));
            v1 = a.y / (1.f + __expf(-v1));
        }
        *(float2*)&C[base] = make_float2(v0, v1);
    };
    mma_body(A, B, K, N, col0, arow, epi);
}

// ---------------- expert GEMM 1: hh = x @ w1[e] + b1 -------------------------
__global__ __launch_bounds__(256)
void gemm_tf_e1(const float* __restrict__ x, const float* __restrict__ w1,
                const float* __restrict__ b1, float* __restrict__ hh)
{
    const int e = blockIdx.z;
    const int cnt = g_counts[e];
    const int rt = blockIdx.y * 128;
    if (rt >= cnt) return;
    const int off = g_offsets[e];
    const int col0 = blockIdx.x * 64;
    const float* B = w1 + (size_t)e * D_DIM * F_DIM;
    const float* b1e = b1 + (size_t)e * F_DIM;
    auto arow = [&](int r) {
        int rr = rt + r; if (rr >= cnt) rr = cnt - 1;
        return g_p2t[off + rr];
    };
    auto epi = [&](int m, int c, float v0, float v1) {
        if (rt + m >= cnt) return;
        const int gc = col0 + c;
        const size_t base = (size_t)(off + rt + m) * F_DIM + gc;
        *(float2*)&hh[base] = make_float2(v0 + b1e[gc], v1 + b1e[gc + 1]);
    };
    mma_body(x, B, D_DIM, F_DIM, col0, arow, epi);
}

// ---------------- expert GEMM 2 + residual scatter ---------------------------
__global__ __launch_bounds__(256)
void gemm_tf_e2(const float* __restrict__ hh, const float* __restrict__ w2,
                const float* __restrict__ b2, const float* __restrict__ res_scale,
                const float* __restrict__ x, float* __restrict__ moe)
{
    const int e = blockIdx.z;
    const int cnt = g_counts[e];
    const int rt = blockIdx.y * 128;
    if (rt >= cnt) return;
    const int off = g_offsets[e];
    const int col0 = blockIdx.x * 64;
    const float* B = w2 + (size_t)e * F_DIM * D_DIM;
    const float* b2e = b2 + (size_t)e * D_DIM;
    const float rsc = res_scale[e];
    auto arow = [&](int r) {
        int rr = rt + r; if (rr >= cnt) rr = cnt - 1;
        return off + rr;
    };
    auto epi = [&](int m, int c, float v0, float v1) {
        if (rt + m >= cnt) return;
        const int tok = g_p2t[off + rt + m];
        const int gc = col0 + c;
        const size_t base = (size_t)tok * D_DIM + gc;
        float2 xr = *(const float2*)&x[base];
        *(float2*)&moe[base] = make_float2((v0 + b2e[gc]) * rsc + xr.x,
                                           (v1 + b2e[gc + 1]) * rsc + xr.y);
    };
    mma_body(hh, B, F_DIM, D_DIM, col0, arow, epi);
}

// ================= TF32 MMA flash attention ==================================
// smem: Q [128][68] fp32, K chunks [64][68] x2, V chunks [64][72] x2
#define AQ_OFF 0
#define AK_OFF(b) (34816 + (b) * 17408)
#define AV_OFF(b) (69632 + (b) * 18432)
#define AQSC 106496
#define ATTN_SMEM (106496 + 512)

__global__ __launch_bounds__(256, 1)
void attn_tf(const float* __restrict__ q, const float* __restrict__ k,
             const float* __restrict__ v, const float* __restrict__ scale_w,
             float* __restrict__ out)
{
    extern __shared__ char smem[];
    const uint32_t sb = smem_u32(smem);
    float* qsc = (float*)(smem + AQSC);
    const int t = threadIdx.x, lane = t & 31, warp = t >> 5;
    const int h = blockIdx.y & 15, b = blockIdx.y >> 4;
    const int qtok0 = b * S_LEN + blockIdx.x * 128;
    const size_t headoff = (size_t)h * 64;

    {
        const int row = t >> 1, half = t & 1;
        const float* src = q + (size_t)(qtok0 + row) * D_DIM + headoff + half * 32;
        const uint32_t dq = AQ_OFF + (uint32_t)row * 272 + half * 128;
#pragma unroll
        for (int i = 0; i < 8; ++i)
            CP_ASYNC16(sb + dq + i * 16, src + i * 4);
        CP_COMMIT();
    }
    auto issueKV = [&](int c, int buf) {
        const int row = t >> 2, seg = t & 3;
        const size_t so = (size_t)(b * S_LEN + c * 64 + row) * D_DIM + headoff + seg * 16;
        const uint32_t dk = AK_OFF(buf) + (uint32_t)row * 272 + seg * 64;
        const uint32_t dv = AV_OFF(buf) + (uint32_t)row * 288 + seg * 64;
#pragma unroll
        for (int i = 0; i < 4; ++i) {
            CP_ASYNC16(sb + dk + i * 16, k + so + i * 4);
            CP_ASYNC16(sb + dv + i * 16, v + so + i * 4);
        }
        CP_COMMIT();
    };
    issueKV(0, 0);
    CP_WAIT1();
    __syncthreads();

    if (t < 128) {
        float s = 0.f;
        const float* qrow = (const float*)(smem + AQ_OFF) + t * 68;
        for (int d = 0; d < 64; ++d) s += qrow[d] * __ldg(&scale_w[h * 64 + d]);
        qsc[t] = 0.25f / (1.f + __expf(-s));
    }

    const int a_row_l = (lane & 7) + ((lane >> 3) & 1) * 8;
    const int a_k_l   = ((lane >> 4) & 1) * 4;
    const int r0loc = warp * 16 + (lane >> 2);

    float s[8][4];
    float o[8][4] = {};
    float m0 = -1e30f, m1 = -1e30f, l0 = 0.f, l1 = 0.f;

    for (int c = 0; c < 16; ++c) {
        CP_WAIT0();
        __syncthreads();
        if (c < 15) issueKV(c + 1, (c + 1) & 1);
        const uint32_t kb = sb + AK_OFF(c & 1);
        const uint32_t vb = sb + AV_OFF(c & 1);

        // ---- S = Q K^T ----
#pragma unroll
        for (int j = 0; j < 8; ++j) { s[j][0] = s[j][1] = s[j][2] = s[j][3] = 0.f; }
#pragma unroll
        for (int kk = 0; kk < 8; ++kk) {
            uint32_t a[4];
            const uint32_t ao = (uint32_t)(warp * 16 + a_row_l) * 272 + (kk * 8 + a_k_l) * 4;
            ldsm4(a, sb + AQ_OFF + ao);
#pragma unroll
            for (int p = 0; p < 4; ++p) {
                const uint32_t ro = (uint32_t)(p * 16 + a_row_l) * 272 + (kk * 8 + a_k_l) * 4;
                uint32_t br[4];
                ldsm4(br, kb + ro);
                mma_tf32(s[2 * p],     a, br[0], br[2]);
                mma_tf32(s[2 * p + 1], a, br[1], br[3]);
            }
        }
        const float f0 = qsc[r0loc], f1 = qsc[r0loc + 8];
#pragma unroll
        for (int j = 0; j < 8; ++j) { s[j][0] *= f0; s[j][1] *= f0; s[j][2] *= f1; s[j][3] *= f1; }
        float rm0 = -1e30f, rm1 = -1e30f;
#pragma unroll
        for (int j = 0; j < 8; ++j) {
            rm0 = fmaxf(rm0, fmaxf(s[j][0], s[j][1]));
            rm1 = fmaxf(rm1, fmaxf(s[j][2], s[j][3]));
        }
        rm0 = fmaxf(rm0, __shfl_xor_sync(0xffffffffu, rm0, 1));
        rm0 = fmaxf(rm0, __shfl_xor_sync(0xffffffffu, rm0, 2));
        rm1 = fmaxf(rm1, __shfl_xor_sync(0xffffffffu, rm1, 1));
        rm1 = fmaxf(rm1, __shfl_xor_sync(0xffffffffu, rm1, 2));
        const float nm0 = fmaxf(m0, rm0), nm1 = fmaxf(m1, rm1);
        const float e0 = __expf(m0 - nm0), e1v = __expf(m1 - nm1);
        float sum0 = 0.f, sum1 = 0.f;
#pragma unroll
        for (int j = 0; j < 8; ++j) {
            s[j][0] = __expf(s[j][0] - nm0); sum0 += s[j][0];
            s[j][1] = __expf(s[j][1] - nm0); sum0 += s[j][1];
            s[j][2] = __expf(s[j][2] - nm1); sum1 += s[j][2];
            s[j][3] = __expf(s[j][3] - nm1); sum1 += s[j][3];
        }
        sum0 += __shfl_xor_sync(0xffffffffu, sum0, 1);
        sum0 += __shfl_xor_sync(0xffffffffu, sum0, 2);
        sum1 += __shfl_xor_sync(0xffffffffu, sum1, 1);
        sum1 += __shfl_xor_sync(0xffffffffu, sum1, 2);
        l0 = l0 * e0 + sum0;
        l1 = l1 * e1v + sum1;
        m0 = nm0; m1 = nm1;
#pragma unroll
        for (int j = 0; j < 8; ++j) { o[j][0] *= e0; o[j][1] *= e0; o[j][2] *= e1v; o[j][3] *= e1v; }

        // ---- O += P V ----
#pragma unroll
        for (int kk = 0; kk < 8; ++kk) {
            const int jpar = lane & 1;
            const int srcl  = (lane & 28) | ((lane & 3) >> 1);
            const int srcl2 = srcl + 2;
            float f0a = __shfl_sync(0xffffffffu, s[kk][0], srcl);
            float f1a = __shfl_sync(0xffffffffu, s[kk][1], srcl);
            float f2a = __shfl_sync(0xffffffffu, s[kk][2], srcl);
            float f3a = __shfl_sync(0xffffffffu, s[kk][3], srcl);
            float g0a = __shfl_sync(0xffffffffu, s[kk][0], srcl2);
            float g1a = __shfl_sync(0xffffffffu, s[kk][1], srcl2);
            float g2a = __shfl_sync(0xffffffffu, s[kk][2], srcl2);
            float g3a = __shfl_sync(0xffffffffu, s[kk][3], srcl2);
            uint32_t a[4];
            a[0] = __float_as_uint(jpar ? f1a : f0a);
            a[1] = __float_as_uint(jpar ? f3a : f2a);
            a[2] = __float_as_uint(jpar ? g1a : g0a);
            a[3] = __float_as_uint(jpar ? g3a : g2a);
#pragma unroll
            for (int nj = 0; nj < 8; ++nj) {
                const uint32_t b0a = vb + (uint32_t)(kk * 8 + (lane & 3)) * 288
                                   + (uint32_t)(nj * 8 + (lane >> 2)) * 4;
                const uint32_t b0 = __float_as_uint(lds32(b0a));
                const uint32_t b1 = __float_as_uint(lds32(b0a + 4 * 288));
                mma_tf32(o[nj], a, b0, b1);
            }
        }
    }

    const float inv0 = 1.f / l0, inv1 = 1.f / l1;
    const int tok0 = qtok0 + r0loc, tok1 = tok0 + 8;
#pragma unroll
    for (int j = 0; j < 8; ++j) {
        const size_t col = headoff + j * 8 + (lane & 3) * 2;
        *(float2*)&out[(size_t)tok0 * D_DIM + col] = make_float2(o[j][0] * inv0, o[j][1] * inv0);
        *(float2*)&out[(size_t)tok1 * D_DIM + col] = make_float2(o[j][2] * inv1, o[j][3] * inv1);
    }
}

// ---------------- layernorm over residual sum -------------------------------
__global__ void ln2_kernel(const float* __restrict__ a, const float* __restrict__ b,
                           const float* __restrict__ g, const float* __restrict__ be,
                           float* __restrict__ out, int D)
{
    const int row = blockIdx.x, t = threadIdx.x;
    __shared__ float red[256];
    __shared__ float s_mean, s_rstd;
    float s1 = 0.f, s2 = 0.f;
    for (int i = t; i < D; i += 256) {
        float v = a[(size_t)row * D + i] + b[(size_t)row * D + i];
        s1 += v; s2 += v * v;
    }
    red[t] = s1; __syncthreads();
    for (int o = 128; o; o >>= 1) { if (t < o) red[t] += red[t + o]; __syncthreads(); }
    if (t == 0) s_mean = red[0] / D;
    __syncthreads();
    red[t] = s2; __syncthreads();
    for (int o = 128; o; o >>= 1) { if (t < o) red[t] += red[t + o]; __syncthreads(); }
    if (t == 0) {
        float var = red[0] / D - s_mean * s_mean;
        s_rstd = rsqrtf(var + 1e-5f);
    }
    __syncthreads();
    for (int i = t; i < D; i += 256) {
        float v = a[(size_t)row * D + i] + b[(size_t)row * D + i];
        out[(size_t)row * D + i] = (v - s_mean) * s_rstd * g[i] + be[i];
    }
}

// ---------------- MoE routing ------------------------------------------------
__global__ void reset_kernel() { if (threadIdx.x < N_EXP) g_counts[threadIdx.x] = 0; }

__global__ void moe_gate_kernel(const float* __restrict__ x, const float* __restrict__ W,
                                const float* __restrict__ bias)
{
    const int n = blockIdx.x, t = threadIdx.x;
    const int e = t >> 5, lane = t & 31;
    float acc = 0.f;
    for (int d = lane; d < D_DIM; d += 32) acc += x[(size_t)n * D_DIM + d] * W[d * N_EXP + e];
    for (int o = 16; o; o >>= 1) acc += __shfl_down_sync(0xffffffffu, acc, o);
    __shared__ float lg[N_EXP];
    if (lane == 0) lg[e] = acc + bias[e];
    __syncthreads();
    if (t == 0) {
        int i1 = 0; float v1 = lg[0];
        for (int i = 1; i < N_EXP; ++i) if (lg[i] > v1) { v1 = lg[i]; i1 = i; }
        int i2 = -1; float v2 = -1e30f;
        for (int i = 0; i < N_EXP; ++i) {
            if (i == i1) continue;
            if (lg[i] > v2) { v2 = lg[i]; i2 = i; }
        }
        int c = (i1 > i2) ? i1 : i2;
        g_chosen[n] = c;
        atomicAdd(&g_counts[c], 1);
    }
}

__global__ void scan_kernel()
{
    if (threadIdx.x == 0) {
        int s = 0;
        for (int e = 0; e < N_EXP; ++e) { g_offsets[e] = s; g_cursor[e] = s; s += g_counts[e]; }
    }
}

__global__ void scatter_kernel()
{
    int n = blockIdx.x * 256 + threadIdx.x;
    if (n < N_TOK) {
        int c = g_chosen[n];
        int p = atomicAdd(&g_cursor[c], 1);
        g_p2t[p] = n;
        g_p2e[p] = c;
    }
}

// ---------------- per-expert LN + exact GELU (in-place) ----------------------
__global__ void ln_gelu_kernel(float* __restrict__ hh, const float* __restrict__ ln_g,
                               const float* __restrict__ ln_b)
{
    const int p = blockIdx.x, t = threadIdx.x;
    const int e = g_p2e[p];
    float* row = hh + (size_t)p * F_DIM;
    const float* gg = ln_g + (size_t)e * F_DIM;
    const float* bb = ln_b + (size_t)e * F_DIM;
    __shared__ float red[256];
    __shared__ float s_mean, s_rstd;
    float s1 = 0.f, s2 = 0.f;
    for (int i = t; i < F_DIM; i += 256) { float v = row[i]; s1 += v; s2 += v * v; }
    red[t] = s1; __syncthreads();
    for (int o = 128; o; o >>= 1) { if (t < o) red[t] += red[t + o]; __syncthreads(); }
    if (t == 0) s_mean = red[0] / F_DIM;
    __syncthreads();
    red[t] = s2; __syncthreads();
    for (int o = 128; o; o >>= 1) { if (t < o) red[t] += red[t + o]; __syncthreads(); }
    if (t == 0) {
        float var = red[0] / F_DIM - s_mean * s_mean;
        s_rstd = rsqrtf(var + 1e-5f);
    }
    __syncthreads();
    for (int i = t; i < F_DIM; i += 256) {
        float tv = (row[i] - s_mean) * s_rstd * gg[i] + bb[i];
        row[i] = 0.5f * tv * (1.f + erff(tv * 0.70710678118654752f));
    }
}

// ---------------- host launcher ---------------------------------------------
extern "C" void kernel_launch(void* const* d_in, const int* in_sizes, int n_in,
                              void* d_out, int out_size)
{
    (void)in_sizes; (void)n_in; (void)out_size;
    const float* src        = (const float*)d_in[0];
    const float* q_w        = (const float*)d_in[1];
    const float* k_w        = (const float*)d_in[2];
    const float* v_w        = (const float*)d_in[3];
    const float* out_w      = (const float*)d_in[4];
    const float* gate_w     = (const float*)d_in[5];
    const float* gate_b     = (const float*)d_in[6];
    const float* scale_w    = (const float*)d_in[7];
    const float* n1_g       = (const float*)d_in[8];
    const float* n1_b       = (const float*)d_in[9];
    const float* n2_g       = (const float*)d_in[10];
    const float* n2_b       = (const float*)d_in[11];
    const float* moe_gate_w = (const float*)d_in[12];
    const float* moe_gate_b = (const float*)d_in[13];
    const float* w1         = (const float*)d_in[14];
    const float* b1         = (const float*)d_in[15];
    const float* ln_g       = (const float*)d_in[16];
    const float* ln_b       = (const float*)d_in[17];
    const float* w2         = (const float*)d_in[18];
    const float* b2         = (const float*)d_in[19];
    const float* res_scale  = (const float*)d_in[20];

    float *qb, *kb, *vb, *attno, *gated, *attnp, *xb, *hhb, *moeb;
    cudaGetSymbolAddress((void**)&qb, g_q);
    cudaGetSymbolAddress((void**)&kb, g_k);
    cudaGetSymbolAddress((void**)&vb, g_v);
    cudaGetSymbolAddress((void**)&attno, g_attno);
    cudaGetSymbolAddress((void**)&gated, g_gated);
    cudaGetSymbolAddress((void**)&attnp, g_attnp);
    cudaGetSymbolAddress((void**)&xb, g_x);
    cudaGetSymbolAddress((void**)&hhb, g_hh);
    cudaGetSymbolAddress((void**)&moeb, g_moe);

    cudaFuncSetAttribute(attn_tf, cudaFuncAttributeMaxDynamicSharedMemorySize, ATTN_SMEM);
    cudaFuncSetAttribute(gemm_tf_dense, cudaFuncAttributeMaxDynamicSharedMemorySize, TF_SMEM);
    cudaFuncSetAttribute(gemm_tf_e1, cudaFuncAttributeMaxDynamicSharedMemorySize, TF_SMEM);
    cudaFuncSetAttribute(gemm_tf_e2, cudaFuncAttributeMaxDynamicSharedMemorySize, TF_SMEM);

    reset_kernel<<<1, 32>>>();

    // QKV (batched z=3)
    {
        DenseArgs da = {};
        da.B[0] = q_w; da.B[1] = k_w; da.B[2] = v_w;
        da.C[0] = qb; da.C[1] = kb; da.C[2] = vb;
        gemm_tf_dense<<<dim3(16, 16, 3), 256, TF_SMEM>>>(src, da, D_DIM, D_DIM);
    }

    attn_tf<<<dim3(8, 32), 256, ATTN_SMEM>>>(qb, kb, vb, scale_w, attno);

    // gated = sigmoid(attno @ gate_w + gate_b) * attno
    {
        DenseArgs da = {};
        da.B[0] = gate_w; da.bias[0] = gate_b; da.aux[0] = attno;
        da.C[0] = gated; da.mode[0] = 1;
        gemm_tf_dense<<<dim3(16, 16, 1), 256, TF_SMEM>>>(attno, da, D_DIM, D_DIM);
    }

    // attnp = gated @ out_w
    {
        DenseArgs da = {};
        da.B[0] = out_w; da.C[0] = attnp; da.mode[0] = 0;
        gemm_tf_dense<<<dim3(16, 16, 1), 256, TF_SMEM>>>(gated, da, D_DIM, D_DIM);
    }

    ln2_kernel<<<N_TOK, 256>>>(src, attnp, n1_g, n1_b, xb, D_DIM);

    moe_gate_kernel<<<N_TOK, 256>>>(xb, moe_gate_w, moe_gate_b);
    scan_kernel<<<1, 32>>>();
    scatter_kernel<<<N_TOK / 256, 256>>>();

    gemm_tf_e1<<<dim3(F_DIM / 64, N_TOK / 128, N_EXP), 256, TF_SMEM>>>(xb, w1, b1, hhb);
    ln_gelu_kernel<<<N_TOK, 256>>>(hhb, ln_g, ln_b);
    gemm_tf_e2<<<dim3(D_DIM / 64, N_TOK / 128, N_EXP), 256, TF_SMEM>>>(
        hhb, w2, b2, res_scale, xb, moeb);

    ln2_kernel<<<N_TOK, 256>>>(xb, moeb, n2_g, n2_b, (float*)d_out, D_DIM);
}